// round 3
// baseline (speedup 1.0000x reference)
#include <cuda_runtime.h>

#define NN  100000
#define EE  1600000
#define FIN 32
#define HH  128

// ---------------- scratch (static device globals; no allocs) ----------------
__device__ float g_h  [(size_t)NN * HH];
__device__ float g_pre[(size_t)NN * HH];
__device__ float g_agg[(size_t)NN * HH];
__device__ float g_res[(size_t)NN * HH];
__device__ int   g_deg[NN];
__device__ int   g_off[NN + 1];
__device__ int   g_cur[NN];
__device__ int   g_csr[EE];
__device__ int   g_bsum[256];

// buffer selectors (resolved in device code; host never touches symbols)
#define SEL_AGG  0
#define SEL_H    1
#define SEL_PRE  2
#define SEL_RES  3
#define SEL_EXT  4
#define SEL_NULL 5

__device__ __forceinline__ const float* sel_c(int s, const float* ext) {
    switch (s) {
        case SEL_AGG: return g_agg;
        case SEL_H:   return g_h;
        case SEL_PRE: return g_pre;
        case SEL_RES: return g_res;
        case SEL_EXT: return ext;
        default:      return nullptr;
    }
}
__device__ __forceinline__ float* sel_m(int s, float* ext) {
    switch (s) {
        case SEL_AGG: return g_agg;
        case SEL_H:   return g_h;
        case SEL_PRE: return g_pre;
        case SEL_RES: return g_res;
        case SEL_EXT: return ext;
        default:      return nullptr;
    }
}

// edge fetch: i64 flag selects int64 (8B) vs int32 (4B) storage
__device__ __forceinline__ int edge_at(const void* ei, size_t pos, int i64) {
    if (i64) return (int)((const long long*)ei)[pos];
    return ((const int*)ei)[pos];
}

// ---------------- CSR build ----------------
__global__ void k_zero_deg() {
    int i = blockIdx.x * blockDim.x + threadIdx.x;
    if (i < NN) g_deg[i] = 0;
}

__global__ void k_count(const void* __restrict__ ei, int i64) {
    int e = blockIdx.x * blockDim.x + threadIdx.x;
    if (e < EE) {
        int dst = edge_at(ei, (size_t)EE + e, i64);
        if ((unsigned)dst < (unsigned)NN)   // defensive: never trap
            atomicAdd(&g_deg[dst], 1);
    }
}

__global__ void k_scan1() {
    __shared__ int s[1024];
    int t = threadIdx.x;
    int i = blockIdx.x * 1024 + t;
    int v = (i < NN) ? g_deg[i] : 0;
    s[t] = v;
    __syncthreads();
    for (int off = 1; off < 1024; off <<= 1) {
        int u = (t >= off) ? s[t - off] : 0;
        __syncthreads();
        s[t] += u;
        __syncthreads();
    }
    if (i < NN) g_off[i + 1] = s[t];
    if (t == 1023) g_bsum[blockIdx.x] = s[1023];
}

__global__ void k_scan2(int nb) {
    __shared__ int s[256];
    int t = threadIdx.x;
    if (t < nb) s[t] = g_bsum[t];
    __syncthreads();
    if (t == 0) {
        int run = 0;
        for (int b = 0; b < nb; b++) { int tmp = s[b]; s[b] = run; run += tmp; }
    }
    __syncthreads();
    if (t < nb) g_bsum[t] = s[t];
}

__global__ void k_scan3() {
    int i = blockIdx.x * blockDim.x + threadIdx.x;
    if (i >= NN) return;
    int v = g_off[i + 1] + g_bsum[i >> 10];
    g_off[i + 1] = v;
    g_cur[i] = v - g_deg[i];  // exclusive start of bucket i
    if (i == 0) g_off[0] = 0;
}

__global__ void k_fill(const void* __restrict__ ei, int i64) {
    int e = blockIdx.x * blockDim.x + threadIdx.x;
    if (e < EE) {
        int src = edge_at(ei, (size_t)e, i64);
        int dst = edge_at(ei, (size_t)EE + e, i64);
        if ((unsigned)dst < (unsigned)NN && (unsigned)src < (unsigned)NN) {
            int pos = atomicAdd(&g_cur[dst], 1);
            if ((unsigned)pos < (unsigned)EE) g_csr[pos] = src;
        }
    }
}

// ---------------- gather / mean-aggregate ----------------
// one warp per node, lane = feature (F=32); x(ext) -> g_agg
__global__ void k_gather32(const float* __restrict__ x) {
    int idx  = blockIdx.x * blockDim.x + threadIdx.x;
    int node = idx >> 5;
    int lane = idx & 31;
    if (node >= NN) return;
    int beg = g_off[node], end = g_off[node + 1];
    float acc = 0.f;
    for (int e = beg; e < end; e++) {
        int s = g_csr[e];
        acc += __ldg(&x[(size_t)s * FIN + lane]);
    }
    float inv = 1.f / fmaxf((float)(end - beg), 1.f);
    g_agg[(size_t)node * FIN + lane] = acc * inv;
}

// one warp per node, float4 per lane (H=128); g_h -> g_agg
__global__ void k_gather128() {
    int idx  = blockIdx.x * blockDim.x + threadIdx.x;
    int node = idx >> 5;
    int lane = idx & 31;
    if (node >= NN) return;
    int beg = g_off[node], end = g_off[node + 1];
    const float4* h4 = (const float4*)g_h;
    float4 acc = make_float4(0.f, 0.f, 0.f, 0.f);
    for (int e = beg; e < end; e++) {
        int s = g_csr[e];
        float4 v = __ldg(&h4[s * 32 + lane]);
        acc.x += v.x; acc.y += v.y; acc.z += v.z; acc.w += v.w;
    }
    float inv = 1.f / fmaxf((float)(end - beg), 1.f);
    acc.x *= inv; acc.y *= inv; acc.z *= inv; acc.w *= inv;
    ((float4*)g_agg)[node * 32 + lane] = acc;
}

// ---------------- tiled SGEMM: C = [A1 | A2] @ [W1 ; W2] + bias ----------------
// BM=128, BN=128, BK=16, 256 threads, 8x8 per thread
#define BM 128
#define BN 128
#define BK 16
#define ASTRIDE (BM + 4)

__global__ __launch_bounds__(256) void k_sgemm(
    int selA1, int K1,
    int selA2, int K2,
    const float* __restrict__ Aext,
    const float* __restrict__ W1, const float* __restrict__ W2,
    const float* __restrict__ bias,
    int selC, int M)
{
    __shared__ float As[BK][ASTRIDE];
    __shared__ float Bs[BK][BN];
    const float* A1 = sel_c(selA1, Aext);
    const float* A2 = sel_c(selA2, Aext);
    float* C = sel_m(selC, nullptr);

    int tid = threadIdx.x;
    int tx = tid & 15;        // N dim: 16 threads * 8
    int ty = tid >> 4;        // M dim: 16 threads * 8
    int m0 = blockIdx.x * BM;
    float acc[8][8];
    #pragma unroll
    for (int i = 0; i < 8; i++)
        #pragma unroll
        for (int j = 0; j < 8; j++) acc[i][j] = 0.f;

    int Ktot = K1 + K2;
    for (int k0 = 0; k0 < Ktot; k0 += BK) {
        const float* A; const float* W; int lda; int kb;
        if (k0 < K1) { A = A1; W = W1; lda = K1; kb = k0; }
        else         { A = A2; W = W2; lda = K2; kb = k0 - K1; }

        // load A tile (transposed into As[k][m])
        {
            int m  = tid >> 2;           // 0..63
            int kq = (tid & 3) * 4;      // 0,4,8,12
            #pragma unroll
            for (int s = 0; s < 2; s++) {
                int mm = m + s * 64;
                float4 v = make_float4(0.f, 0.f, 0.f, 0.f);
                if (m0 + mm < M)
                    v = *(const float4*)&A[(size_t)(m0 + mm) * lda + kb + kq];
                As[kq + 0][mm] = v.x;
                As[kq + 1][mm] = v.y;
                As[kq + 2][mm] = v.z;
                As[kq + 3][mm] = v.w;
            }
        }
        // load B tile Bs[k][n]
        {
            int k = tid >> 5;            // 0..7
            int n = (tid & 31) * 4;
            #pragma unroll
            for (int s = 0; s < 2; s++) {
                int kk = k + s * 8;
                *(float4*)&Bs[kk][n] = *(const float4*)&W[(size_t)(kb + kk) * BN + n];
            }
        }
        __syncthreads();

        #pragma unroll
        for (int k = 0; k < BK; k++) {
            float a[8], b[8];
            *(float4*)&a[0] = *(const float4*)&As[k][ty * 8 + 0];
            *(float4*)&a[4] = *(const float4*)&As[k][ty * 8 + 4];
            *(float4*)&b[0] = *(const float4*)&Bs[k][tx * 8 + 0];
            *(float4*)&b[4] = *(const float4*)&Bs[k][tx * 8 + 4];
            #pragma unroll
            for (int i = 0; i < 8; i++)
                #pragma unroll
                for (int j = 0; j < 8; j++)
                    acc[i][j] = fmaf(a[i], b[j], acc[i][j]);
        }
        __syncthreads();
    }

    #pragma unroll
    for (int i = 0; i < 8; i++) {
        int m = m0 + ty * 8 + i;
        if (m >= M) break;
        #pragma unroll
        for (int j = 0; j < 8; j += 4) {
            int n = tx * 8 + j;
            float4 v;
            v.x = acc[i][j + 0]; v.y = acc[i][j + 1];
            v.z = acc[i][j + 2]; v.w = acc[i][j + 3];
            if (bias) {
                v.x += bias[n + 0]; v.y += bias[n + 1];
                v.z += bias[n + 2]; v.w += bias[n + 3];
            }
            *(float4*)&C[(size_t)m * BN + n] = v;
        }
    }
}

// ---------------- LayerNorm + ReLU + residual (warp per node) ----------------
__global__ void k_ln(int selRes, int selOut, float* outExt,
                     const float* __restrict__ g, const float* __restrict__ b)
{
    int idx  = blockIdx.x * blockDim.x + threadIdx.x;
    int node = idx >> 5;
    int lane = idx & 31;
    if (node >= NN) return;
    const float* res = sel_c(selRes, nullptr);
    float* out = sel_m(selOut, outExt);

    const float4* p4 = (const float4*)(g_pre + (size_t)node * HH);
    float4 v = p4[lane];
    float s  = v.x + v.y + v.z + v.w;
    float sq = v.x * v.x + v.y * v.y + v.z * v.z + v.w * v.w;
    #pragma unroll
    for (int o = 16; o > 0; o >>= 1) {
        s  += __shfl_xor_sync(0xFFFFFFFFu, s,  o);
        sq += __shfl_xor_sync(0xFFFFFFFFu, sq, o);
    }
    float mu  = s * (1.f / 128.f);
    float var = sq * (1.f / 128.f) - mu * mu;
    float r   = rsqrtf(var + 1e-5f);
    float4 gg = ((const float4*)g)[lane];
    float4 bb = ((const float4*)b)[lane];
    float4 rr = ((const float4*)(res + (size_t)node * HH))[lane];
    float4 o4;
    o4.x = fmaxf((v.x - mu) * r * gg.x + bb.x, 0.f) + rr.x;
    o4.y = fmaxf((v.y - mu) * r * gg.y + bb.y, 0.f) + rr.y;
    o4.z = fmaxf((v.z - mu) * r * gg.z + bb.z, 0.f) + rr.z;
    o4.w = fmaxf((v.w - mu) * r * gg.w + bb.w, 0.f) + rr.w;
    ((float4*)(out + (size_t)node * HH))[lane] = o4;
}

// ---------------- head: yhat = h @ Wh + bh ----------------
__global__ void k_head(int selH, const float* __restrict__ hExt,
                       const float* __restrict__ Wh,
                       const float* __restrict__ bh, float* __restrict__ y)
{
    int idx  = blockIdx.x * blockDim.x + threadIdx.x;
    int node = idx >> 5;
    int lane = idx & 31;
    if (node >= NN) return;
    const float* h = sel_c(selH, hExt);
    float4 v = ((const float4*)(h + (size_t)node * HH))[lane];
    float4 w = ((const float4*)Wh)[lane];
    float s = v.x * w.x + v.y * w.y + v.z * w.z + v.w * w.w;
    #pragma unroll
    for (int o = 16; o > 0; o >>= 1)
        s += __shfl_xor_sync(0xFFFFFFFFu, s, o);
    if (lane == 0) y[node] = s + bh[0];
}

// ---------------- launch ----------------
extern "C" void kernel_launch(void* const* d_in, const int* in_sizes, int n_in,
                              void* d_out, int out_size)
{
    const float* x   = (const float*)d_in[0];
    const void*  ei  = d_in[1];
    // dtype detection: element count is 2*EE for both int32 and int64; JAX
    // default (x64 disabled) emits int32. If the harness ever reports the
    // byte-based count (4*EE elements would mean int64 stored as 2 words),
    // fall back. Primary assumption: int32.
    int ei64 = (in_sizes[1] == 4 * EE) ? 1 : 0;

    const float* Wl0 = (const float*)d_in[2];
    const float* bl0 = (const float*)d_in[3];
    const float* Wr0 = (const float*)d_in[4];
    const float* g0  = (const float*)d_in[5];
    const float* be0 = (const float*)d_in[6];
    const float* Wl1 = (const float*)d_in[7];
    const float* bl1 = (const float*)d_in[8];
    const float* Wr1 = (const float*)d_in[9];
    const float* g1  = (const float*)d_in[10];
    const float* be1 = (const float*)d_in[11];
    const float* Wl2 = (const float*)d_in[12];
    const float* bl2 = (const float*)d_in[13];
    const float* Wr2 = (const float*)d_in[14];
    const float* g2  = (const float*)d_in[15];
    const float* be2 = (const float*)d_in[16];
    const float* Wpr = (const float*)d_in[17];
    const float* Wh  = (const float*)d_in[18];
    const float* bh  = (const float*)d_in[19];

    float* out = (float*)d_out;
    bool   big = (out_size >= NN + NN * HH);
    float* yhat   = out;
    float* hout   = big ? (out + NN) : nullptr;   // final h destination if room
    int    selHF  = big ? SEL_EXT : SEL_H;

    const int T = 256;
    int gridN   = (NN + T - 1) / T;          // node-parallel
    int gridE   = (EE + T - 1) / T;          // edge-parallel
    int gridW   = (NN * 32 + T - 1) / T;     // warp-per-node
    int nb      = (NN + 1023) / 1024;        // scan blocks
    int gridG   = (NN + BM - 1) / BM;        // gemm blocks

    // ---- CSR build ----
    k_zero_deg<<<gridN, T>>>();
    k_count<<<gridE, T>>>(ei, ei64);
    k_scan1<<<nb, 1024>>>();
    k_scan2<<<1, 256>>>(nb);
    k_scan3<<<gridN, T>>>();
    k_fill<<<gridE, T>>>(ei, ei64);

    // ---- layer 0 ----
    k_gather32<<<gridW, T>>>(x);
    k_sgemm<<<gridG, 256>>>(SEL_AGG, FIN, SEL_EXT, FIN, x, Wl0, Wr0, bl0, SEL_PRE, NN);
    k_sgemm<<<gridG, 256>>>(SEL_EXT, FIN, SEL_NULL, 0, x, Wpr, nullptr, nullptr, SEL_RES, NN);
    k_ln<<<gridW, T>>>(SEL_RES, SEL_H, nullptr, g0, be0);

    // ---- layer 1 ----
    k_gather128<<<gridW, T>>>();
    k_sgemm<<<gridG, 256>>>(SEL_AGG, HH, SEL_H, HH, nullptr, Wl1, Wr1, bl1, SEL_PRE, NN);
    k_ln<<<gridW, T>>>(SEL_H, SEL_H, nullptr, g1, be1);

    // ---- layer 2 ----
    k_gather128<<<gridW, T>>>();
    k_sgemm<<<gridG, 256>>>(SEL_AGG, HH, SEL_H, HH, nullptr, Wl2, Wr2, bl2, SEL_PRE, NN);
    k_ln<<<gridW, T>>>(SEL_H, selHF, hout, g2, be2);

    // ---- head ----
    k_head<<<gridW, T>>>(selHF, hout, Wh, bh, yhat);
}